// round 17
// baseline (speedup 1.0000x reference)
#include <cuda_runtime.h>

#define BB 2048

// ---------------------------------------------------------------------------
// Fully fused kernel: FIR + recurrence + direct transposed store.
// 16 lanes/element, 2 warps/SMSP. Pair-batched UNCLAMPED cur prefetch
// (safe for all pairs except the last, which needs no prefetch).
// Rings per lane:
//   R[4]  feedback: taps j=4r+3..4r+6 (0 for j>64), scatter input tbPrev
//   RX[4] FIR:      lags d=4r+3..4r+6 (0 for d>63), scatter input cur(s-1)
// Lane0 local: FB taps 1 (W1L consume-patch), 2 (W2L release);
//   FIR lags 0,1,2 from cur(s+2),cur(s+1),cur(s); chain seed xoffC.
// Output: lane0 predicated scalar STG of mfr*th to out[t*BB+e] each step.
// ---------------------------------------------------------------------------
#define STEP(p, cm1, cc0, cc1, cc2) { \
    /* serial chain */ \
    float xx_ = fmaf(W1L, thPrev, yq[(p)&1]); \
    float u_  = xx_ * xx_; \
    float s1_ = fmaf(c1, xx_, c0); \
    float s2_ = fmaf(c3, xx_, c2); \
    float pv_ = fmaf(u_, s2_, s1_); \
    float pr_ = fmaxf(pv_, 0.0f); \
    float th_; asm("tanh.approx.f32 %0, %1;" : "=f"(th_) : "f"(pr_)); \
    float fo_ = mfr * th_; \
    if (r == 0) obase[(p) * BB] = fo_; \
    float tb_ = __shfl_sync(0xffffffffu, th_, 0, 16); \
    /* feedback ring: deferred seed + scatter with 1-step-old broadcast */ \
    R[((p)+3)&3] = hUPrev * u15; \
    R[((p)+0)&3] = fmaf(W[0], tbPrev, R[((p)+0)&3]); \
    R[((p)+1)&3] = fmaf(W[1], tbPrev, R[((p)+1)&3]); \
    R[((p)+2)&3] = fmaf(W[2], tbPrev, R[((p)+2)&3]); \
    R[((p)+3)&3] = fmaf(W[3], tbPrev, R[((p)+3)&3]); \
    float valRel_ = R[(p)&3]; \
    float hU_ = __shfl_down_sync(0xffffffffu, valRel_, 1, 16); \
    /* FIR ring: input cur(s-1), no shfl on input */ \
    RX[((p)+3)&3] = hXPrev * u15; \
    RX[((p)+0)&3] = fmaf(GX[0], (cm1), RX[((p)+0)&3]); \
    RX[((p)+1)&3] = fmaf(GX[1], (cm1), RX[((p)+1)&3]); \
    RX[((p)+2)&3] = fmaf(GX[2], (cm1), RX[((p)+2)&3]); \
    RX[((p)+3)&3] = fmaf(GX[3], (cm1), RX[((p)+3)&3]); \
    float xRel_ = RX[(p)&3]; \
    float hX_ = __shfl_down_sync(0xffffffffu, xRel_, 1, 16); \
    /* assemble yq for target step s+2 */ \
    float t0_ = fmaf(A0, (cc2), xoffC); \
    float t1_ = fmaf(A1, (cc1), t0_); \
    float t2_ = fmaf(A2, (cc0), t1_); \
    float t3_ = t2_ + xRel_; \
    float t4_ = fmaf(W2L, th_, valRel_); \
    yq[(p)&1] = t3_ + t4_; \
    thPrev = th_; tbPrev = tb_; hUPrev = hU_; hXPrev = hX_; \
}

// even block of a pair: window cprev, ca[0..7], cb[0..1]
#define S8E() \
    STEP(0, cprev, ca[0], ca[1], ca[2]) \
    STEP(1, ca[0], ca[1], ca[2], ca[3]) \
    STEP(2, ca[1], ca[2], ca[3], ca[4]) \
    STEP(3, ca[2], ca[3], ca[4], ca[5]) \
    STEP(4, ca[3], ca[4], ca[5], ca[6]) \
    STEP(5, ca[4], ca[5], ca[6], ca[7]) \
    STEP(6, ca[5], ca[6], ca[7], cb[0]) \
    STEP(7, ca[6], ca[7], cb[0], cb[1]) \
    obase += 8 * BB;

// odd block: window ca[7], cb[0..7], na[0..1]
#define S8O() \
    STEP(0, ca[7], cb[0], cb[1], cb[2]) \
    STEP(1, cb[0], cb[1], cb[2], cb[3]) \
    STEP(2, cb[1], cb[2], cb[3], cb[4]) \
    STEP(3, cb[2], cb[3], cb[4], cb[5]) \
    STEP(4, cb[3], cb[4], cb[5], cb[6]) \
    STEP(5, cb[4], cb[5], cb[6], cb[7]) \
    STEP(6, cb[5], cb[6], cb[7], na[0]) \
    STEP(7, cb[6], cb[7], na[0], na[1]) \
    obase += 8 * BB;

__global__ void __launch_bounds__(256) rec_kernel(
    const float* __restrict__ cur,
    const float* __restrict__ a,
    const float* __restrict__ b_lag,
    const float* __restrict__ poly_coeff,
    const float* __restrict__ b_act,
    const float* __restrict__ max_cur,
    const float* __restrict__ max_fr,
    float* __restrict__ out,
    int T)
{
    const int tid = threadIdx.x;
    const int r   = tid & 15;                       // lane within 16-lane group
    const int e   = blockIdx.x * 16 + (tid >> 4);   // element index

    const float inv_mc = 1.0f / __ldg(&max_cur[0]);
    const float mfr    = __ldg(&max_fr[0]);
    float c0 = __ldg(&poly_coeff[0]); c0 *= c0;
    float c1 = __ldg(&poly_coeff[1]); c1 *= c1;
    float c2 = __ldg(&poly_coeff[2]); c2 *= c2;
    float c3 = __ldg(&poly_coeff[3]); c3 *= c3;
    const float cwm   = 1000.0f * inv_mc * mfr;     // FB weights absorb mfr
    const float xoffC = -__ldg(&b_act[0]) * inv_mc;

    // feedback: lane r owns taps j = 4r+3+k (k=0..3)
    float W[4];
#pragma unroll
    for (int k = 0; k < 4; ++k) {
        int j = 4 * r + 3 + k;
        W[k] = (j <= 64) ? cwm * __ldg(&b_lag[64 - j]) : 0.0f;
    }
    const float W1L = (r == 0)  ? cwm * __ldg(&b_lag[63]) : 0.0f;
    const float W2L = (r == 0)  ? cwm * __ldg(&b_lag[62]) : 0.0f;

    // FIR: lane r owns lags d = 4r+3+k; weight inv_mc * a[63-d]
    float GX[4];
#pragma unroll
    for (int k = 0; k < 4; ++k) {
        int idx = 60 - 4 * r - k;                    // 63 - d
        GX[k] = (idx >= 0) ? inv_mc * __ldg(&a[idx]) : 0.0f;
    }
    const float A0 = (r == 0) ? inv_mc * __ldg(&a[63]) : 0.0f;
    const float A1 = (r == 0) ? inv_mc * __ldg(&a[62]) : 0.0f;
    const float A2 = (r == 0) ? inv_mc * __ldg(&a[61]) : 0.0f;

    const float u15 = (r == 15) ? 0.0f : 1.0f;

    float R[4], RX[4];
#pragma unroll
    for (int k = 0; k < 4; ++k) { R[k] = 0.0f; RX[k] = 0.0f; }
    float thPrev = 0.0f, tbPrev = 0.0f, hUPrev = 0.0f, hXPrev = 0.0f;

    const float* cbase = cur + e;                   // cur[t][e]
    float* obase = out + e;                         // out[t][e], lane0 stores
    const int Tm1 = T - 1;

    // initial window (clamped; one-time): cprev=cur(-1)=0, ca=cur(0..7), cb=cur(8..15)
    float cprev = 0.0f;
    float ca[8], cb[8], na[8], nb[8];
#pragma unroll
    for (int j = 0; j < 8; ++j) {
        int t0c = (j     <= Tm1) ? j     : Tm1;
        int t1c = (j + 8 <= Tm1) ? j + 8 : Tm1;
        ca[j] = __ldg(cbase + (size_t)t0c * BB);
        cb[j] = __ldg(cbase + (size_t)t1c * BB);
        na[j] = 0.0f; nb[j] = 0.0f;                  // avoid uninit use in last pair
    }

    // yq init: x(0), x(1) from local taps only (all history zero)
    float yq[2];
    yq[0] = fmaf(A0, ca[0], xoffC);
    yq[1] = fmaf(A0, ca[1], fmaf(A1, ca[0], xoffC));

    const int npair = T >> 4;

    // pairs 0..npair-2: UNCLAMPED prefetch of pair m+1 (max index 16*npair-1 <= T-1)
    for (int m = 0; m < npair - 1; ++m) {
        const int base = 16 * (m + 1);
#pragma unroll
        for (int j = 0; j < 8; ++j) {
            na[j] = __ldg(cbase + (size_t)(base + j) * BB);
            nb[j] = __ldg(cbase + (size_t)(base + 8 + j) * BB);
        }
        S8E()
        S8O()
        cprev = cb[7];
#pragma unroll
        for (int j = 0; j < 8; ++j) { ca[j] = na[j]; cb[j] = nb[j]; }
    }

    // last full pair: no prefetch (na/nb stale-but-finite; those yq slots are dead)
    if (npair > 0) {
        S8E()
        S8O()
        cprev = cb[7];
    }

    // ---- generic tail (T mod 16 steps; empty for T=2000) ----
    const int t0tail = npair * 16;
    const int tail   = T - t0tail;
    if (tail > 0) {
        // ct[k] = cur(t0tail - 1 + k), k = 0..17 (clamped loads)
        float ct[18];
        ct[0] = cprev;
#pragma unroll 1
        for (int k = 1; k < 18; ++k) {
            int tl = t0tail - 1 + k;
            if (tl > Tm1) tl = Tm1;
            if (tl < 0) tl = 0;
            ct[k] = __ldg(cbase + (size_t)tl * BB);
        }
        float Rd[4], RXd[4];
#pragma unroll
        for (int k = 0; k < 4; ++k) { Rd[k] = R[k]; RXd[k] = RX[k]; }
#pragma unroll 1
        for (int tt = 0; tt < tail; ++tt) {
            int t = t0tail + tt;
            int p = t & 3;
            float cm1 = ct[tt];
            float xx = fmaf(W1L, thPrev, yq[t & 1]);
            float u_  = xx * xx;
            float s1_ = fmaf(c1, xx, c0);
            float s2_ = fmaf(c3, xx, c2);
            float pv  = fmaf(u_, s2_, s1_);
            float pr  = fmaxf(pv, 0.0f);
            float th; asm("tanh.approx.f32 %0, %1;" : "=f"(th) : "f"(pr));
            if (r == 0) out[(size_t)t * BB + e] = mfr * th;
            float tbn = __shfl_sync(0xffffffffu, th, 0, 16);
            Rd[(p + 3) & 3] = hUPrev * u15;
#pragma unroll 1
            for (int k = 0; k < 4; ++k)
                Rd[(p + k) & 3] = fmaf(W[k], tbPrev, Rd[(p + k) & 3]);
            float valRel = Rd[p];
            float hU = __shfl_down_sync(0xffffffffu, valRel, 1, 16);
            RXd[(p + 3) & 3] = hXPrev * u15;
#pragma unroll 1
            for (int k = 0; k < 4; ++k)
                RXd[(p + k) & 3] = fmaf(GX[k], cm1, RXd[(p + k) & 3]);
            float xRel = RXd[p];
            float hX = __shfl_down_sync(0xffffffffu, xRel, 1, 16);
            float t0 = fmaf(A0, ct[tt + 3], xoffC);
            float t1 = fmaf(A1, ct[tt + 2], t0);
            float t2 = fmaf(A2, ct[tt + 1], t1);
            float t3 = t2 + xRel;
            float t4 = fmaf(W2L, th, valRel);
            yq[t & 1] = t3 + t4;
            thPrev = th; tbPrev = tbn; hUPrev = hU; hXPrev = hX;
        }
    }
}

// ---------------------------------------------------------------------------
extern "C" void kernel_launch(void* const* d_in, const int* in_sizes, int n_in,
                              void* d_out, int out_size)
{
    const float* currents = (const float*)d_in[0];
    const float* a        = (const float*)d_in[1];
    const float* b_lag    = (const float*)d_in[2];
    const float* poly     = (const float*)d_in[3];
    const float* b_act    = (const float*)d_in[4];
    const float* max_cur  = (const float*)d_in[5];
    const float* max_fr   = (const float*)d_in[6];
    float* out = (float*)d_out;

    const int T = in_sizes[0] / BB;   // 2000

    // single fused kernel: 16 lanes/element, 16 elements per 256-thread
    // block -> 128 blocks, 1024 warps -> 2 warps per SMSP chip-wide.
    rec_kernel<<<BB / 16, 256>>>(currents, a, b_lag, poly, b_act,
                                 max_cur, max_fr, out, T);
}